// round 3
// baseline (speedup 1.0000x reference)
#include <cuda_runtime.h>

// GAE backward scan as a parallel suffix scan of affine maps.
// gae_t = delta_t + c_t * gae_{t+1},  c_t = GAMMA*LMBDA*nd_t  (nd in {0,1})
// R3: register-lean mask encoding + high occupancy, DEFAULT cache policy
// (R2's __ldcs/__stcs streaming hints regressed DRAM throughput 66%->58%).

#define GAMMA 0.99f
#define LMBDA 0.95f
#define KCOEF (GAMMA * LMBDA)   // 0.9405f

constexpr int T_LEN   = 2048;
constexpr int THREADS = 256;
constexpr int VPT     = T_LEN / THREADS;  // 8 elements per thread

__global__ __launch_bounds__(THREADS, 7)
void gae_kernel(const float* __restrict__ reward,
                const int*   __restrict__ terminated,
                const float* __restrict__ value,
                const float* __restrict__ next_value,
                float*       __restrict__ adv_out,
                float*       __restrict__ ret_out)
{
    const int tid  = threadIdx.x;
    const int lane = tid & 31;
    const int warp = tid >> 5;

    const long long base = (long long)blockIdx.x * T_LEN + (long long)tid * VPT;

    // ---- Load + fuse: keep only delta[8], v[8], and an 8-bit nd mask ----
    float delta[VPT], v[VPT];
    unsigned mask = 0;
    {
        const float4* r4  = reinterpret_cast<const float4*>(reward     + base);
        const float4* v4  = reinterpret_cast<const float4*>(value      + base);
        const float4* nv4 = reinterpret_cast<const float4*>(next_value + base);
        const int4*   t4  = reinterpret_cast<const int4*>(terminated   + base);
        #pragma unroll
        for (int q = 0; q < VPT / 4; ++q) {
            float4 rr = r4[q];
            float4 vv = v4[q];
            float4 nn = nv4[q];
            int4   tt = t4[q];
            v[q*4+0] = vv.x; v[q*4+1] = vv.y; v[q*4+2] = vv.z; v[q*4+3] = vv.w;
            // delta = r - v + GAMMA*nv*nd ; nd = !terminated
            delta[q*4+0] = (tt.x == 0) ? fmaf(GAMMA, nn.x, rr.x - vv.x) : (rr.x - vv.x);
            delta[q*4+1] = (tt.y == 0) ? fmaf(GAMMA, nn.y, rr.y - vv.y) : (rr.y - vv.y);
            delta[q*4+2] = (tt.z == 0) ? fmaf(GAMMA, nn.z, rr.z - vv.z) : (rr.z - vv.z);
            delta[q*4+3] = (tt.w == 0) ? fmaf(GAMMA, nn.w, rr.w - vv.w) : (rr.w - vv.w);
            mask |= (tt.x == 0 ? 1u : 0u) << (q*4+0);
            mask |= (tt.y == 0 ? 1u : 0u) << (q*4+1);
            mask |= (tt.z == 0 ? 1u : 0u) << (q*4+2);
            mask |= (tt.w == 0 ? 1u : 0u) << (q*4+3);
        }
    }

    // ---- Fold chunk into one affine composite (j=0 earliest/outermost) ----
    float A = 1.0f, B = 0.0f;
    #pragma unroll
    for (int j = 0; j < VPT; ++j) {
        B = fmaf(A, delta[j], B);
        A = ((mask >> j) & 1u) ? A * KCOEF : 0.0f;
    }

    // ---- Warp-level inclusive SUFFIX scan (self = earlier = outer) ----
    const unsigned FULL = 0xffffffffu;
    float Ai = A, Bi = B;
    #pragma unroll
    for (int off = 1; off < 32; off <<= 1) {
        float Ao = __shfl_down_sync(FULL, Ai, off);
        float Bo = __shfl_down_sync(FULL, Bi, off);
        if (lane + off < 32) {
            Bi = fmaf(Ai, Bo, Bi);
            Ai = Ai * Ao;
        }
    }
    // Exclusive within warp: composite of lanes (lane+1 .. 31)
    float Ae = __shfl_down_sync(FULL, Ai, 1);
    float Be = __shfl_down_sync(FULL, Bi, 1);
    if (lane == 31) { Ae = 1.0f; Be = 0.0f; }

    // ---- Cross-warp combine (8 warps) ----
    __shared__ float sA[8], sB[8], gIn[8];
    if (lane == 0) { sA[warp] = Ai; sB[warp] = Bi; }
    __syncthreads();
    if (tid < 8) {
        float g = 0.0f;
        #pragma unroll
        for (int w = 7; w > 0; --w)
            if (w > tid) g = fmaf(sA[w], g, sB[w]);
        gIn[tid] = g;
    }
    __syncthreads();

    // Carry entering this thread's chunk (gae at chunk-end + 1)
    float g = fmaf(Ae, gIn[warp], Be);

    // ---- Replay chunk backward, materialize advantages ----
    float adv[VPT];
    #pragma unroll
    for (int j = VPT - 1; j >= 0; --j) {
        float gk = ((mask >> j) & 1u) ? fmaf(KCOEF, g, delta[j]) : delta[j];
        g = gk;
        adv[j] = gk;
    }

    // ---- Stores (default policy): advantages, then returns = adv + value ----
    {
        float4* a4 = reinterpret_cast<float4*>(adv_out + base);
        float4* o4 = reinterpret_cast<float4*>(ret_out + base);
        #pragma unroll
        for (int q = 0; q < VPT / 4; ++q) {
            float4 av, rt;
            av.x = adv[q*4+0]; av.y = adv[q*4+1]; av.z = adv[q*4+2]; av.w = adv[q*4+3];
            rt.x = av.x + v[q*4+0];
            rt.y = av.y + v[q*4+1];
            rt.z = av.z + v[q*4+2];
            rt.w = av.w + v[q*4+3];
            a4[q] = av;
            o4[q] = rt;
        }
    }
}

extern "C" void kernel_launch(void* const* d_in, const int* in_sizes, int n_in,
                              void* d_out, int out_size)
{
    const float* reward     = (const float*)d_in[0];
    const int*   terminated = (const int*)  d_in[1];
    const float* value      = (const float*)d_in[2];
    const float* next_value = (const float*)d_in[3];

    const int n = in_sizes[0];          // B * T
    const int B = n / T_LEN;

    float* adv_out = (float*)d_out;          // advantages: first n elements
    float* ret_out = (float*)d_out + n;      // returns:    next n elements

    gae_kernel<<<B, THREADS>>>(reward, terminated, value, next_value,
                               adv_out, ret_out);
}

// round 4
// speedup vs baseline: 1.2464x; 1.2464x over previous
#include <cuda_runtime.h>

// GAE backward scan as a parallel suffix scan of affine maps.
// gae_t = delta_t + c_t * gae_{t+1},  c_t = GAMMA*LMBDA*nd_t  (nd in {0,1})
//
// R4: fully-coalesced loads (VPT=4, one float4 per thread per array, 512
// threads per row) + occupancy pinned to 48 warps/SM (3x512 blocks) via a
// 64KB dynamic-smem cap. Evidence: occ 68% (R1) beat occ 88% (R2/R3) by
// ~15% DRAM throughput -> cross-CTA L1tex queue contention.

#define GAMMA 0.99f
#define LMBDA 0.95f
#define KCOEF (GAMMA * LMBDA)   // 0.9405f

constexpr int T_LEN   = 2048;
constexpr int THREADS = 512;
constexpr int VPT     = T_LEN / THREADS;  // 4 elements per thread
constexpr int NWARP   = THREADS / 32;     // 16
constexpr size_t SMEM_BYTES = 64 * 1024;  // caps residency at 3 blocks/SM

__global__ __launch_bounds__(THREADS)
void gae_kernel(const float* __restrict__ reward,
                const int*   __restrict__ terminated,
                const float* __restrict__ value,
                const float* __restrict__ next_value,
                float*       __restrict__ adv_out,
                float*       __restrict__ ret_out)
{
    extern __shared__ float smem[];
    float* sA  = smem;            // [NWARP]
    float* sB  = smem + NWARP;    // [NWARP]
    float* gIn = smem + 2*NWARP;  // [NWARP]

    const int tid  = threadIdx.x;
    const int lane = tid & 31;
    const int warp = tid >> 5;

    const long long base = (long long)blockIdx.x * T_LEN + (long long)tid * VPT;

    // ---- One float4/int4 per array: perfectly coalesced, full sectors ----
    float4 rr = *reinterpret_cast<const float4*>(reward     + base);
    float4 vv = *reinterpret_cast<const float4*>(value      + base);
    float4 nn = *reinterpret_cast<const float4*>(next_value + base);
    int4   tt = *reinterpret_cast<const int4*>(terminated   + base);

    float v[VPT] = {vv.x, vv.y, vv.z, vv.w};
    float delta[VPT];
    unsigned mask = 0;
    // delta = r - v + GAMMA*nv*nd ; nd = !terminated
    delta[0] = (tt.x == 0) ? fmaf(GAMMA, nn.x, rr.x - vv.x) : (rr.x - vv.x);
    delta[1] = (tt.y == 0) ? fmaf(GAMMA, nn.y, rr.y - vv.y) : (rr.y - vv.y);
    delta[2] = (tt.z == 0) ? fmaf(GAMMA, nn.z, rr.z - vv.z) : (rr.z - vv.z);
    delta[3] = (tt.w == 0) ? fmaf(GAMMA, nn.w, rr.w - vv.w) : (rr.w - vv.w);
    mask |= (tt.x == 0 ? 1u : 0u) << 0;
    mask |= (tt.y == 0 ? 1u : 0u) << 1;
    mask |= (tt.z == 0 ? 1u : 0u) << 2;
    mask |= (tt.w == 0 ? 1u : 0u) << 3;

    // ---- Fold chunk into one affine composite (j=0 earliest/outermost) ----
    float A = 1.0f, B = 0.0f;
    #pragma unroll
    for (int j = 0; j < VPT; ++j) {
        B = fmaf(A, delta[j], B);
        A = ((mask >> j) & 1u) ? A * KCOEF : 0.0f;
    }

    // ---- Warp-level inclusive SUFFIX scan (self = earlier = outer) ----
    const unsigned FULL = 0xffffffffu;
    float Ai = A, Bi = B;
    #pragma unroll
    for (int off = 1; off < 32; off <<= 1) {
        float Ao = __shfl_down_sync(FULL, Ai, off);
        float Bo = __shfl_down_sync(FULL, Bi, off);
        if (lane + off < 32) {
            Bi = fmaf(Ai, Bo, Bi);
            Ai = Ai * Ao;
        }
    }
    // Exclusive within warp: composite of lanes (lane+1 .. 31)
    float Ae = __shfl_down_sync(FULL, Ai, 1);
    float Be = __shfl_down_sync(FULL, Bi, 1);
    if (lane == 31) { Ae = 1.0f; Be = 0.0f; }

    // ---- Cross-warp combine (16 warps) ----
    if (lane == 0) { sA[warp] = Ai; sB[warp] = Bi; }
    __syncthreads();
    if (tid < NWARP) {
        float g = 0.0f;
        #pragma unroll
        for (int w = NWARP - 1; w > 0; --w)
            if (w > tid) g = fmaf(sA[w], g, sB[w]);
        gIn[tid] = g;
    }
    __syncthreads();

    // Carry entering this thread's chunk (gae just past chunk end)
    float g = fmaf(Ae, gIn[warp], Be);

    // ---- Replay chunk backward, materialize advantages ----
    float adv[VPT];
    #pragma unroll
    for (int j = VPT - 1; j >= 0; --j) {
        g = ((mask >> j) & 1u) ? fmaf(KCOEF, g, delta[j]) : delta[j];
        adv[j] = g;
    }

    // ---- Coalesced stores: advantages, then returns = adv + value ----
    float4 av, rt;
    av.x = adv[0]; av.y = adv[1]; av.z = adv[2]; av.w = adv[3];
    rt.x = av.x + v[0];
    rt.y = av.y + v[1];
    rt.z = av.z + v[2];
    rt.w = av.w + v[3];
    *reinterpret_cast<float4*>(adv_out + base) = av;
    *reinterpret_cast<float4*>(ret_out + base) = rt;
}

extern "C" void kernel_launch(void* const* d_in, const int* in_sizes, int n_in,
                              void* d_out, int out_size)
{
    const float* reward     = (const float*)d_in[0];
    const int*   terminated = (const int*)  d_in[1];
    const float* value      = (const float*)d_in[2];
    const float* next_value = (const float*)d_in[3];

    const int n = in_sizes[0];          // B * T
    const int B = n / T_LEN;

    float* adv_out = (float*)d_out;          // advantages: first n elements
    float* ret_out = (float*)d_out + n;      // returns:    next n elements

    cudaFuncSetAttribute(gae_kernel,
                         cudaFuncAttributeMaxDynamicSharedMemorySize,
                         (int)SMEM_BYTES);

    gae_kernel<<<B, THREADS, SMEM_BYTES>>>(reward, terminated, value,
                                           next_value, adv_out, ret_out);
}